// round 15
// baseline (speedup 1.0000x reference)
#include <cuda_runtime.h>

#define NCAP (1 << 20)          // capacity (reference uses exactly 2^20 points)
#define NBINS 32768             // 15-bit spatial bucket (32^3 grid)
#define HASH_MASK 0x7FFFFu
#define P2 2654435761u
#define P3 805459861u

// ---------------- scratch (allocation-free: __device__ globals) ----------------
// g_hist is zero at module load; scan_blocks re-zeroes it after consuming it,
// so every graph replay sees a zeroed histogram (deterministic).
__device__ unsigned int g_hist[NBINS];
__device__ unsigned int g_offsets[NBINS];   // per-block-exclusive after scan_blocks
__device__ unsigned int g_blocksum[32];
__device__ unsigned int g_rankkey[NCAP];    // (key << 17) | within-bucket rank
__device__ float4       g_sortedXyz[NCAP];  // xyz + original index in .w

static __device__ __constant__ float c_resf[16] = {
    16.f, 20.f, 25.f, 32.f, 40.f, 50.f, 64.f, 80.f,
    101.f, 128.f, 161.f, 203.f, 256.f, 322.f, 406.f, 512.f
};

__device__ __forceinline__ unsigned bucket_key(float x, float y, float z) {
    unsigned cx = min((unsigned)(x * 32.0f), 31u);
    unsigned cy = min((unsigned)(y * 32.0f), 31u);
    unsigned cz = min((unsigned)(z * 32.0f), 31u);
    return (cx << 10) | (cy << 5) | cz;
}

// ---------------- pass 1: histogram + rank capture (4 points/thread) ----------------
__global__ void hist_kernel(const float4* __restrict__ xyz4,
                            const float*  __restrict__ xyz, int n_pts) {
    int g = blockIdx.x * blockDim.x + threadIdx.x;   // group of 4 points
    int base = g * 4;
    if (base >= n_pts) return;
    if (base + 3 < n_pts) {
        float4 a = __ldg(xyz4 + g * 3 + 0);
        float4 b = __ldg(xyz4 + g * 3 + 1);
        float4 c = __ldg(xyz4 + g * 3 + 2);
        unsigned k0 = bucket_key(a.x, a.y, a.z);
        unsigned k1 = bucket_key(a.w, b.x, b.y);
        unsigned k2 = bucket_key(b.z, b.w, c.x);
        unsigned k3 = bucket_key(c.y, c.z, c.w);
        unsigned r0 = atomicAdd(&g_hist[k0], 1u);
        unsigned r1 = atomicAdd(&g_hist[k1], 1u);
        unsigned r2 = atomicAdd(&g_hist[k2], 1u);
        unsigned r3 = atomicAdd(&g_hist[k3], 1u);
        uint4 rk = make_uint4((k0 << 17) | r0, (k1 << 17) | r1,
                              (k2 << 17) | r2, (k3 << 17) | r3);
        *(uint4*)&g_rankkey[base] = rk;
    } else {
        for (int i = base; i < n_pts; i++) {
            float x = xyz[3 * i + 0], y = xyz[3 * i + 1], z = xyz[3 * i + 2];
            unsigned key = bucket_key(x, y, z);
            unsigned rank = atomicAdd(&g_hist[key], 1u);
            g_rankkey[i] = (key << 17) | rank;
        }
    }
}

// ---------------- pass 2: per-block exclusive scan of 1024 contiguous bins ---------
__global__ void scan_blocks_kernel() {
    __shared__ unsigned s[1024];
    int t = threadIdx.x;
    int i = blockIdx.x * 1024 + t;
    unsigned v = g_hist[i];
    g_hist[i] = 0u;                      // re-zero for next graph replay
    s[t] = v;
    __syncthreads();
    for (int d = 1; d < 1024; d <<= 1) {
        unsigned u = (t >= d) ? s[t - d] : 0u;
        __syncthreads();
        s[t] += u;
        __syncthreads();
    }
    g_offsets[i] = s[t] - v;             // exclusive within block
    if (t == 1023) g_blocksum[blockIdx.x] = s[t];
}

// ---------------- pass 3: scatter (atomic-free, 4 points/thread, fused fixup) -------
__global__ void scatter_kernel(const float4* __restrict__ xyz4,
                               const float*  __restrict__ xyz, int n_pts) {
    __shared__ unsigned bex[32];
    if (threadIdx.x < 32) {
        unsigned v = g_blocksum[threadIdx.x];
        unsigned x = v;
        #pragma unroll
        for (int d = 1; d < 32; d <<= 1) {
            unsigned u = __shfl_up_sync(0xFFFFFFFFu, x, d);
            if (threadIdx.x >= d) x += u;
        }
        bex[threadIdx.x] = x - v;        // exclusive prefix of block sums
    }
    __syncthreads();

    int g = blockIdx.x * blockDim.x + threadIdx.x;
    int base = g * 4;
    if (base >= n_pts) return;
    if (base + 3 < n_pts) {
        float4 a = __ldg(xyz4 + g * 3 + 0);
        float4 b = __ldg(xyz4 + g * 3 + 1);
        float4 c = __ldg(xyz4 + g * 3 + 2);
        uint4 rk = *(const uint4*)&g_rankkey[base];

        unsigned k0 = rk.x >> 17, k1 = rk.y >> 17, k2 = rk.z >> 17, k3 = rk.w >> 17;
        unsigned p0 = g_offsets[k0] + bex[k0 >> 10] + (rk.x & 0x1FFFFu);
        unsigned p1 = g_offsets[k1] + bex[k1 >> 10] + (rk.y & 0x1FFFFu);
        unsigned p2 = g_offsets[k2] + bex[k2 >> 10] + (rk.z & 0x1FFFFu);
        unsigned p3 = g_offsets[k3] + bex[k3 >> 10] + (rk.w & 0x1FFFFu);

        g_sortedXyz[p0] = make_float4(a.x, a.y, a.z, __int_as_float(base + 0));
        g_sortedXyz[p1] = make_float4(a.w, b.x, b.y, __int_as_float(base + 1));
        g_sortedXyz[p2] = make_float4(b.z, b.w, c.x, __int_as_float(base + 2));
        g_sortedXyz[p3] = make_float4(c.y, c.z, c.w, __int_as_float(base + 3));
    } else {
        for (int i = base; i < n_pts; i++) {
            float x = xyz[3 * i + 0], y = xyz[3 * i + 1], z = xyz[3 * i + 2];
            unsigned rk   = g_rankkey[i];
            unsigned key  = rk >> 17;
            unsigned pos  = g_offsets[key] + bex[key >> 10] + (rk & 0x1FFFFu);
            g_sortedXyz[pos] = make_float4(x, y, z, __int_as_float(i));
        }
    }
}

// Gather + trilerp for one (point, level). Identical to the proven R11 inner loop.
__device__ __forceinline__ float2 encode_pt(
    const float2* __restrict__ tables, int level,
    float x, float y, float z)
{
    float resf = c_resf[level];
    float cell = __fdiv_rn(1.0f, resf);

    // exact match to jnp.floor(x / cell)
    float fx = floorf(__fdiv_rn(x, cell));
    float fy = floorf(__fdiv_rn(y, cell));
    float fz = floorf(__fdiv_rn(z, cell));
    int ix = (int)fx, iy = (int)fy, iz = (int)fz;

    float minx = fx * cell, miny = fy * cell, minz = fz * cell;
    float dx = __fdividef(x - minx, (minx + cell) - minx);
    float dy = __fdividef(y - miny, (miny + cell) - miny);
    float dz = __fdividef(z - minz, (minz + cell) - minz);

    unsigned hx0 = (unsigned)ix,        hx1 = hx0 + 1u;
    unsigned hy0 = (unsigned)iy * P2,   hy1 = hy0 + P2;
    unsigned hz0 = (unsigned)iz * P3,   hz1 = hz0 + P3;

    const float2* __restrict__ table = tables + ((size_t)level << 19);

    unsigned h00 = (hx0 ^ hy0 ^ hz0) & HASH_MASK;
    unsigned h01 = (hx0 ^ hy0 ^ hz1) & HASH_MASK;
    unsigned h10 = (hx0 ^ hy1 ^ hz0) & HASH_MASK;
    unsigned h11 = (hx0 ^ hy1 ^ hz1) & HASH_MASK;

    float2 e0, e1, e2, e3, e4, e5, e6, e7;

    if (!(hx0 & 1u)) {
        // ix even: x1-corner hash = h ^ 1 -> adjacent entries, one float4 each
        const float4* __restrict__ table4 = (const float4*)table;
        float4 v00 = __ldg(table4 + (h00 >> 1));
        float4 v01 = __ldg(table4 + (h01 >> 1));
        float4 v10 = __ldg(table4 + (h10 >> 1));
        float4 v11 = __ldg(table4 + (h11 >> 1));
        if (h00 & 1u) { e4 = make_float2(v00.x, v00.y); e0 = make_float2(v00.z, v00.w); }
        else          { e0 = make_float2(v00.x, v00.y); e4 = make_float2(v00.z, v00.w); }
        if (h01 & 1u) { e5 = make_float2(v01.x, v01.y); e1 = make_float2(v01.z, v01.w); }
        else          { e1 = make_float2(v01.x, v01.y); e5 = make_float2(v01.z, v01.w); }
        if (h10 & 1u) { e6 = make_float2(v10.x, v10.y); e2 = make_float2(v10.z, v10.w); }
        else          { e2 = make_float2(v10.x, v10.y); e6 = make_float2(v10.z, v10.w); }
        if (h11 & 1u) { e7 = make_float2(v11.x, v11.y); e3 = make_float2(v11.z, v11.w); }
        else          { e3 = make_float2(v11.x, v11.y); e7 = make_float2(v11.z, v11.w); }
    } else {
        unsigned g00 = (hx1 ^ hy0 ^ hz0) & HASH_MASK;
        unsigned g01 = (hx1 ^ hy0 ^ hz1) & HASH_MASK;
        unsigned g10 = (hx1 ^ hy1 ^ hz0) & HASH_MASK;
        unsigned g11 = (hx1 ^ hy1 ^ hz1) & HASH_MASK;
        e0 = __ldg(table + h00);
        e1 = __ldg(table + h01);
        e2 = __ldg(table + h10);
        e3 = __ldg(table + h11);
        e4 = __ldg(table + g00);
        e5 = __ldg(table + g01);
        e6 = __ldg(table + g10);
        e7 = __ldg(table + g11);
    }

    float c00x = fmaf(dx, e4.x - e0.x, e0.x);
    float c00y = fmaf(dx, e4.y - e0.y, e0.y);
    float c01x = fmaf(dx, e5.x - e1.x, e1.x);
    float c01y = fmaf(dx, e5.y - e1.y, e1.y);
    float c10x = fmaf(dx, e6.x - e2.x, e2.x);
    float c10y = fmaf(dx, e6.y - e2.y, e2.y);
    float c11x = fmaf(dx, e7.x - e3.x, e3.x);
    float c11y = fmaf(dx, e7.y - e3.y, e3.y);

    float c0x = fmaf(dy, c10x - c00x, c00x);
    float c0y = fmaf(dy, c10y - c00y, c00y);
    float c1x = fmaf(dy, c11x - c01x, c01x);
    float c1y = fmaf(dy, c11y - c01y, c01y);

    return make_float2(fmaf(dz, c1x - c0x, c0x),
                       fmaf(dz, c1y - c0y, c0y));
}

// ---------------- main: level-major, load-balanced warp pairing ----------------
// block = 512 threads = 16 warps over 64 sorted points (two 32-pt chunks).
// Warp w handles chunk A at level w, then chunk B at level 15-w, so every warp's
// total gather-wavefront count is ~equal -> no barrier bubble from level imbalance.
// Per-warp gather pattern (32 consecutive sorted points at one level) is identical
// to the proven version.
__global__ void __launch_bounds__(512, 4) hashgrid_sorted_kernel(
    const float2* __restrict__ tables,
    float2* __restrict__ out, int n_pts)
{
    __shared__ float2 out_s[64][17];     // padded to dodge bank conflicts
    __shared__ int    orig_s[64];

    const int lane  = threadIdx.x & 31;
    const int w     = threadIdx.x >> 5;  // 0..15
    const int levA  = w;
    const int levB  = 15 - w;
    const int posA  = blockIdx.x * 64 + lane;        // chunk A point
    const int posB  = blockIdx.x * 64 + 32 + lane;   // chunk B point

    // ---- chunk A at level w ----
    {
        bool valid = (posA < n_pts);
        float2 r = make_float2(0.f, 0.f);
        int orig = -1;
        if (valid) {
            float4 v = g_sortedXyz[posA];
            orig = __float_as_int(v.w);
            r = encode_pt(tables, levA, v.x, v.y, v.z);
        }
        out_s[lane][levA] = r;
        if (levA == 0) orig_s[lane] = orig;
    }

    // ---- chunk B at level 15-w ----
    {
        bool valid = (posB < n_pts);
        float2 r = make_float2(0.f, 0.f);
        int orig = -1;
        if (valid) {
            float4 v = g_sortedXyz[posB];
            orig = __float_as_int(v.w);
            r = encode_pt(tables, levB, v.x, v.y, v.z);
        }
        out_s[32 + lane][levB] = r;
        if (levB == 0) orig_s[32 + lane] = orig;     // w == 15
    }

    __syncthreads();

    // cooperative scatter: one full 128B line per point, streamed past L2
    // 512 threads cover 64 points x 16 cols in two passes.
    int c = threadIdx.x & 15;            // level/feature pair 0..15
    #pragma unroll
    for (int half = 0; half < 2; half++) {
        int pl = (threadIdx.x >> 4) + half * 32;     // local point 0..63
        int o  = orig_s[pl];
        if (o >= 0) __stwt(&out[(size_t)o * 16 + c], out_s[pl][c]);
    }
}

extern "C" void kernel_launch(void* const* d_in, const int* in_sizes, int n_in,
                              void* d_out, int out_size)
{
    const float* xyz;
    const float2* tables;
    int n_xyz_elems;
    if (in_sizes[0] < in_sizes[1]) {
        xyz = (const float*)d_in[0];
        tables = (const float2*)d_in[1];
        n_xyz_elems = in_sizes[0];
    } else {
        xyz = (const float*)d_in[1];
        tables = (const float2*)d_in[0];
        n_xyz_elems = in_sizes[1];
    }
    int n_pts = n_xyz_elems / 3;
    int n_grp = (n_pts + 3) / 4;

    hist_kernel<<<(n_grp + 255) / 256, 256>>>((const float4*)xyz, xyz, n_pts);    // #1
    scan_blocks_kernel<<<32, 1024>>>();                                           // #2
    scatter_kernel<<<(n_grp + 255) / 256, 256>>>((const float4*)xyz, xyz, n_pts); // #3
    int n_chunks = (n_pts + 63) / 64;
    hashgrid_sorted_kernel<<<n_chunks, 512>>>(tables, (float2*)d_out, n_pts);     // #4
}

// round 16
// speedup vs baseline: 1.0385x; 1.0385x over previous
#include <cuda_runtime.h>

#define NCAP (1 << 20)          // capacity (reference uses exactly 2^20 points)
#define NBINS 32768             // 15-bit spatial bucket (32^3 grid)
#define HASH_MASK 0x7FFFFu
#define P2 2654435761u
#define P3 805459861u

// ---------------- scratch (allocation-free: __device__ globals) ----------------
// g_hist is zero at module load; scan_blocks re-zeroes it after consuming it,
// so every graph replay sees a zeroed histogram (deterministic).
__device__ unsigned int g_hist[NBINS];
__device__ unsigned int g_offsets[NBINS];   // per-block-exclusive after scan_blocks
__device__ unsigned int g_blocksum[32];
__device__ unsigned int g_rankkey[NCAP];    // (key << 17) | within-bucket rank
__device__ float4       g_sortedXyz[NCAP];  // xyz + original index in .w

static __device__ __constant__ float c_resf[16] = {
    16.f, 20.f, 25.f, 32.f, 40.f, 50.f, 64.f, 80.f,
    101.f, 128.f, 161.f, 203.f, 256.f, 322.f, 406.f, 512.f
};

__device__ __forceinline__ unsigned bucket_key(float x, float y, float z) {
    unsigned cx = min((unsigned)(x * 32.0f), 31u);
    unsigned cy = min((unsigned)(y * 32.0f), 31u);
    unsigned cz = min((unsigned)(z * 32.0f), 31u);
    return (cx << 10) | (cy << 5) | cz;
}

// ---------------- pass 1: histogram + rank capture (4 points/thread) ----------------
__global__ void hist_kernel(const float4* __restrict__ xyz4,
                            const float*  __restrict__ xyz, int n_pts) {
    int g = blockIdx.x * blockDim.x + threadIdx.x;   // group of 4 points
    int base = g * 4;
    if (base >= n_pts) return;
    if (base + 3 < n_pts) {
        float4 a = __ldg(xyz4 + g * 3 + 0);
        float4 b = __ldg(xyz4 + g * 3 + 1);
        float4 c = __ldg(xyz4 + g * 3 + 2);
        unsigned k0 = bucket_key(a.x, a.y, a.z);
        unsigned k1 = bucket_key(a.w, b.x, b.y);
        unsigned k2 = bucket_key(b.z, b.w, c.x);
        unsigned k3 = bucket_key(c.y, c.z, c.w);
        unsigned r0 = atomicAdd(&g_hist[k0], 1u);
        unsigned r1 = atomicAdd(&g_hist[k1], 1u);
        unsigned r2 = atomicAdd(&g_hist[k2], 1u);
        unsigned r3 = atomicAdd(&g_hist[k3], 1u);
        uint4 rk = make_uint4((k0 << 17) | r0, (k1 << 17) | r1,
                              (k2 << 17) | r2, (k3 << 17) | r3);
        *(uint4*)&g_rankkey[base] = rk;
    } else {
        for (int i = base; i < n_pts; i++) {
            float x = xyz[3 * i + 0], y = xyz[3 * i + 1], z = xyz[3 * i + 2];
            unsigned key = bucket_key(x, y, z);
            unsigned rank = atomicAdd(&g_hist[key], 1u);
            g_rankkey[i] = (key << 17) | rank;
        }
    }
}

// ---------------- pass 2: per-block exclusive scan of 1024 contiguous bins ---------
__global__ void scan_blocks_kernel() {
    __shared__ unsigned s[1024];
    int t = threadIdx.x;
    int i = blockIdx.x * 1024 + t;
    unsigned v = g_hist[i];
    g_hist[i] = 0u;                      // re-zero for next graph replay
    s[t] = v;
    __syncthreads();
    for (int d = 1; d < 1024; d <<= 1) {
        unsigned u = (t >= d) ? s[t - d] : 0u;
        __syncthreads();
        s[t] += u;
        __syncthreads();
    }
    g_offsets[i] = s[t] - v;             // exclusive within block
    if (t == 1023) g_blocksum[blockIdx.x] = s[t];
}

// ---------------- pass 3: scatter (atomic-free, 4 points/thread, fused fixup) -------
__global__ void scatter_kernel(const float4* __restrict__ xyz4,
                               const float*  __restrict__ xyz, int n_pts) {
    __shared__ unsigned bex[32];
    if (threadIdx.x < 32) {
        unsigned v = g_blocksum[threadIdx.x];
        unsigned x = v;
        #pragma unroll
        for (int d = 1; d < 32; d <<= 1) {
            unsigned u = __shfl_up_sync(0xFFFFFFFFu, x, d);
            if (threadIdx.x >= d) x += u;
        }
        bex[threadIdx.x] = x - v;        // exclusive prefix of block sums
    }
    __syncthreads();

    int g = blockIdx.x * blockDim.x + threadIdx.x;
    int base = g * 4;
    if (base >= n_pts) return;
    if (base + 3 < n_pts) {
        float4 a = __ldg(xyz4 + g * 3 + 0);
        float4 b = __ldg(xyz4 + g * 3 + 1);
        float4 c = __ldg(xyz4 + g * 3 + 2);
        uint4 rk = *(const uint4*)&g_rankkey[base];

        unsigned k0 = rk.x >> 17, k1 = rk.y >> 17, k2 = rk.z >> 17, k3 = rk.w >> 17;
        unsigned p0 = g_offsets[k0] + bex[k0 >> 10] + (rk.x & 0x1FFFFu);
        unsigned p1 = g_offsets[k1] + bex[k1 >> 10] + (rk.y & 0x1FFFFu);
        unsigned p2 = g_offsets[k2] + bex[k2 >> 10] + (rk.z & 0x1FFFFu);
        unsigned p3 = g_offsets[k3] + bex[k3 >> 10] + (rk.w & 0x1FFFFu);

        g_sortedXyz[p0] = make_float4(a.x, a.y, a.z, __int_as_float(base + 0));
        g_sortedXyz[p1] = make_float4(a.w, b.x, b.y, __int_as_float(base + 1));
        g_sortedXyz[p2] = make_float4(b.z, b.w, c.x, __int_as_float(base + 2));
        g_sortedXyz[p3] = make_float4(c.y, c.z, c.w, __int_as_float(base + 3));
    } else {
        for (int i = base; i < n_pts; i++) {
            float x = xyz[3 * i + 0], y = xyz[3 * i + 1], z = xyz[3 * i + 2];
            unsigned rk   = g_rankkey[i];
            unsigned key  = rk >> 17;
            unsigned pos  = g_offsets[key] + bex[key >> 10] + (rk & 0x1FFFFu);
            g_sortedXyz[pos] = make_float4(x, y, z, __int_as_float(i));
        }
    }
}

// ---------------- main: level-major hash-grid encode over sorted points ----------------
// block = 512 threads = 16 warps; warp w handles level w for 32 consecutive sorted points.
// x-pair trick: PRIMES[0]==1, so for even ix the two x-corners of each (y,z)
// combo sit at table indices h and h^1 -> one 16B-aligned float4 load.
__global__ void __launch_bounds__(512, 4) hashgrid_sorted_kernel(
    const float2* __restrict__ tables,
    float2* __restrict__ out, int n_pts)
{
    __shared__ float2 out_s[32][17];     // padded to dodge bank conflicts
    __shared__ int    orig_s[32];

    const int lane  = threadIdx.x & 31;
    const int level = threadIdx.x >> 5;  // 0..15 (warp-uniform)
    const int pos   = blockIdx.x * 32 + lane;

    bool valid = (pos < n_pts);
    float2 result = make_float2(0.f, 0.f);
    int orig = -1;

    if (valid) {
        float4 v = g_sortedXyz[pos];
        float x = v.x, y = v.y, z = v.z;
        orig = __float_as_int(v.w);

        float resf = c_resf[level];
        float cell = __fdiv_rn(1.0f, resf);

        // exact match to jnp.floor(x / cell)
        float fx = floorf(__fdiv_rn(x, cell));
        float fy = floorf(__fdiv_rn(y, cell));
        float fz = floorf(__fdiv_rn(z, cell));
        int ix = (int)fx, iy = (int)fy, iz = (int)fz;

        float minx = fx * cell, miny = fy * cell, minz = fz * cell;
        float dx = __fdividef(x - minx, (minx + cell) - minx);
        float dy = __fdividef(y - miny, (miny + cell) - miny);
        float dz = __fdividef(z - minz, (minz + cell) - minz);

        unsigned hx0 = (unsigned)ix,        hx1 = hx0 + 1u;
        unsigned hy0 = (unsigned)iy * P2,   hy1 = hy0 + P2;
        unsigned hz0 = (unsigned)iz * P3,   hz1 = hz0 + P3;

        const float2* __restrict__ table = tables + ((size_t)level << 19);

        unsigned h00 = (hx0 ^ hy0 ^ hz0) & HASH_MASK;
        unsigned h01 = (hx0 ^ hy0 ^ hz1) & HASH_MASK;
        unsigned h10 = (hx0 ^ hy1 ^ hz0) & HASH_MASK;
        unsigned h11 = (hx0 ^ hy1 ^ hz1) & HASH_MASK;

        float2 e0, e1, e2, e3, e4, e5, e6, e7;

        if (!(hx0 & 1u)) {
            // ix even: x1-corner hash = h ^ 1 -> adjacent entries, one float4 each
            const float4* __restrict__ table4 = (const float4*)table;
            float4 v00 = __ldg(table4 + (h00 >> 1));
            float4 v01 = __ldg(table4 + (h01 >> 1));
            float4 v10 = __ldg(table4 + (h10 >> 1));
            float4 v11 = __ldg(table4 + (h11 >> 1));
            if (h00 & 1u) { e4 = make_float2(v00.x, v00.y); e0 = make_float2(v00.z, v00.w); }
            else          { e0 = make_float2(v00.x, v00.y); e4 = make_float2(v00.z, v00.w); }
            if (h01 & 1u) { e5 = make_float2(v01.x, v01.y); e1 = make_float2(v01.z, v01.w); }
            else          { e1 = make_float2(v01.x, v01.y); e5 = make_float2(v01.z, v01.w); }
            if (h10 & 1u) { e6 = make_float2(v10.x, v10.y); e2 = make_float2(v10.z, v10.w); }
            else          { e2 = make_float2(v10.x, v10.y); e6 = make_float2(v10.z, v10.w); }
            if (h11 & 1u) { e7 = make_float2(v11.x, v11.y); e3 = make_float2(v11.z, v11.w); }
            else          { e3 = make_float2(v11.x, v11.y); e7 = make_float2(v11.z, v11.w); }
        } else {
            unsigned g00 = (hx1 ^ hy0 ^ hz0) & HASH_MASK;
            unsigned g01 = (hx1 ^ hy0 ^ hz1) & HASH_MASK;
            unsigned g10 = (hx1 ^ hy1 ^ hz0) & HASH_MASK;
            unsigned g11 = (hx1 ^ hy1 ^ hz1) & HASH_MASK;
            e0 = __ldg(table + h00);
            e1 = __ldg(table + h01);
            e2 = __ldg(table + h10);
            e3 = __ldg(table + h11);
            e4 = __ldg(table + g00);
            e5 = __ldg(table + g01);
            e6 = __ldg(table + g10);
            e7 = __ldg(table + g11);
        }

        float c00x = fmaf(dx, e4.x - e0.x, e0.x);
        float c00y = fmaf(dx, e4.y - e0.y, e0.y);
        float c01x = fmaf(dx, e5.x - e1.x, e1.x);
        float c01y = fmaf(dx, e5.y - e1.y, e1.y);
        float c10x = fmaf(dx, e6.x - e2.x, e2.x);
        float c10y = fmaf(dx, e6.y - e2.y, e2.y);
        float c11x = fmaf(dx, e7.x - e3.x, e3.x);
        float c11y = fmaf(dx, e7.y - e3.y, e3.y);

        float c0x = fmaf(dy, c10x - c00x, c00x);
        float c0y = fmaf(dy, c10y - c00y, c00y);
        float c1x = fmaf(dy, c11x - c01x, c01x);
        float c1y = fmaf(dy, c11y - c01y, c01y);

        result = make_float2(fmaf(dz, c1x - c0x, c0x),
                             fmaf(dz, c1y - c0y, c0y));
    }

    out_s[lane][level] = result;
    if (level == 0) orig_s[lane] = orig;
    __syncthreads();

    // cooperative scatter: one full 128B line per point, streamed past L2
    int pl = threadIdx.x >> 4;           // local point 0..31
    int c  = threadIdx.x & 15;           // level/feature pair 0..15
    int o  = orig_s[pl];
    if (o >= 0) __stwt(&out[(size_t)o * 16 + c], out_s[pl][c]);
}

extern "C" void kernel_launch(void* const* d_in, const int* in_sizes, int n_in,
                              void* d_out, int out_size)
{
    const float* xyz;
    const float2* tables;
    int n_xyz_elems;
    if (in_sizes[0] < in_sizes[1]) {
        xyz = (const float*)d_in[0];
        tables = (const float2*)d_in[1];
        n_xyz_elems = in_sizes[0];
    } else {
        xyz = (const float*)d_in[1];
        tables = (const float2*)d_in[0];
        n_xyz_elems = in_sizes[1];
    }
    int n_pts = n_xyz_elems / 3;
    int n_grp = (n_pts + 3) / 4;

    hist_kernel<<<(n_grp + 255) / 256, 256>>>((const float4*)xyz, xyz, n_pts);    // #1
    scan_blocks_kernel<<<32, 1024>>>();                                           // #2
    scatter_kernel<<<(n_grp + 255) / 256, 256>>>((const float4*)xyz, xyz, n_pts); // #3
    int n_chunks = (n_pts + 31) / 32;
    hashgrid_sorted_kernel<<<n_chunks, 512>>>(tables, (float2*)d_out, n_pts);     // #4
}

// round 17
// speedup vs baseline: 1.0471x; 1.0083x over previous
#include <cuda_runtime.h>

#define NCAP (1 << 20)          // capacity (reference uses exactly 2^20 points)
#define NBINS 32768             // 15-bit spatial bucket (32^3 grid)
#define HASH_MASK 0x7FFFFu
#define P2 2654435761u
#define P3 805459861u

// ---------------- scratch (allocation-free: __device__ globals) ----------------
// g_hist is zero at module load; scan_blocks re-zeroes it after consuming it,
// so every graph replay sees a zeroed histogram (deterministic).
__device__ unsigned int g_hist[NBINS];
__device__ unsigned int g_offsets[NBINS];   // per-block-exclusive after scan_blocks
__device__ unsigned int g_blocksum[32];
__device__ unsigned int g_rankkey[NCAP];    // (key << 17) | within-bucket rank
__device__ float4       g_sortedXyz[NCAP];  // xyz + original index in .w

static __device__ __constant__ float c_resf[16] = {
    16.f, 20.f, 25.f, 32.f, 40.f, 50.f, 64.f, 80.f,
    101.f, 128.f, 161.f, 203.f, 256.f, 322.f, 406.f, 512.f
};

__device__ __forceinline__ unsigned bucket_key(float x, float y, float z) {
    unsigned cx = min((unsigned)(x * 32.0f), 31u);
    unsigned cy = min((unsigned)(y * 32.0f), 31u);
    unsigned cz = min((unsigned)(z * 32.0f), 31u);
    return (cx << 10) | (cy << 5) | cz;
}

// ---------------- pass 1: histogram + rank capture (4 points/thread) ----------------
__global__ void hist_kernel(const float4* __restrict__ xyz4,
                            const float*  __restrict__ xyz, int n_pts) {
    int g = blockIdx.x * blockDim.x + threadIdx.x;   // group of 4 points
    int base = g * 4;
    if (base >= n_pts) return;
    if (base + 3 < n_pts) {
        float4 a = __ldg(xyz4 + g * 3 + 0);
        float4 b = __ldg(xyz4 + g * 3 + 1);
        float4 c = __ldg(xyz4 + g * 3 + 2);
        unsigned k0 = bucket_key(a.x, a.y, a.z);
        unsigned k1 = bucket_key(a.w, b.x, b.y);
        unsigned k2 = bucket_key(b.z, b.w, c.x);
        unsigned k3 = bucket_key(c.y, c.z, c.w);
        unsigned r0 = atomicAdd(&g_hist[k0], 1u);
        unsigned r1 = atomicAdd(&g_hist[k1], 1u);
        unsigned r2 = atomicAdd(&g_hist[k2], 1u);
        unsigned r3 = atomicAdd(&g_hist[k3], 1u);
        uint4 rk = make_uint4((k0 << 17) | r0, (k1 << 17) | r1,
                              (k2 << 17) | r2, (k3 << 17) | r3);
        *(uint4*)&g_rankkey[base] = rk;
    } else {
        for (int i = base; i < n_pts; i++) {
            float x = xyz[3 * i + 0], y = xyz[3 * i + 1], z = xyz[3 * i + 2];
            unsigned key = bucket_key(x, y, z);
            unsigned rank = atomicAdd(&g_hist[key], 1u);
            g_rankkey[i] = (key << 17) | rank;
        }
    }
}

// ---------------- pass 2: per-block exclusive scan of 1024 contiguous bins ---------
__global__ void scan_blocks_kernel() {
    __shared__ unsigned s[1024];
    int t = threadIdx.x;
    int i = blockIdx.x * 1024 + t;
    unsigned v = g_hist[i];
    g_hist[i] = 0u;                      // re-zero for next graph replay
    s[t] = v;
    __syncthreads();
    for (int d = 1; d < 1024; d <<= 1) {
        unsigned u = (t >= d) ? s[t - d] : 0u;
        __syncthreads();
        s[t] += u;
        __syncthreads();
    }
    g_offsets[i] = s[t] - v;             // exclusive within block
    if (t == 1023) g_blocksum[blockIdx.x] = s[t];
}

// ---------------- pass 3: scatter (atomic-free, 4 points/thread, fused fixup) -------
__global__ void scatter_kernel(const float4* __restrict__ xyz4,
                               const float*  __restrict__ xyz, int n_pts) {
    __shared__ unsigned bex[32];
    if (threadIdx.x < 32) {
        unsigned v = g_blocksum[threadIdx.x];
        unsigned x = v;
        #pragma unroll
        for (int d = 1; d < 32; d <<= 1) {
            unsigned u = __shfl_up_sync(0xFFFFFFFFu, x, d);
            if (threadIdx.x >= d) x += u;
        }
        bex[threadIdx.x] = x - v;        // exclusive prefix of block sums
    }
    __syncthreads();

    int g = blockIdx.x * blockDim.x + threadIdx.x;
    int base = g * 4;
    if (base >= n_pts) return;
    if (base + 3 < n_pts) {
        float4 a = __ldg(xyz4 + g * 3 + 0);
        float4 b = __ldg(xyz4 + g * 3 + 1);
        float4 c = __ldg(xyz4 + g * 3 + 2);
        uint4 rk = *(const uint4*)&g_rankkey[base];

        unsigned k0 = rk.x >> 17, k1 = rk.y >> 17, k2 = rk.z >> 17, k3 = rk.w >> 17;
        unsigned p0 = g_offsets[k0] + bex[k0 >> 10] + (rk.x & 0x1FFFFu);
        unsigned p1 = g_offsets[k1] + bex[k1 >> 10] + (rk.y & 0x1FFFFu);
        unsigned p2 = g_offsets[k2] + bex[k2 >> 10] + (rk.z & 0x1FFFFu);
        unsigned p3 = g_offsets[k3] + bex[k3 >> 10] + (rk.w & 0x1FFFFu);

        g_sortedXyz[p0] = make_float4(a.x, a.y, a.z, __int_as_float(base + 0));
        g_sortedXyz[p1] = make_float4(a.w, b.x, b.y, __int_as_float(base + 1));
        g_sortedXyz[p2] = make_float4(b.z, b.w, c.x, __int_as_float(base + 2));
        g_sortedXyz[p3] = make_float4(c.y, c.z, c.w, __int_as_float(base + 3));
    } else {
        for (int i = base; i < n_pts; i++) {
            float x = xyz[3 * i + 0], y = xyz[3 * i + 1], z = xyz[3 * i + 2];
            unsigned rk   = g_rankkey[i];
            unsigned key  = rk >> 17;
            unsigned pos  = g_offsets[key] + bex[key >> 10] + (rk & 0x1FFFFu);
            g_sortedXyz[pos] = make_float4(x, y, z, __int_as_float(i));
        }
    }
}

// ---------------- main: level-major hash-grid encode over sorted points ----------------
// block = 512 threads = 16 warps; warp w handles level w for 32 consecutive sorted points.
// x-pair trick: PRIMES[0]==1, so for even ix the two x-corners of each (y,z)
// combo sit at table indices h and h^1 -> one 16B-aligned float4 load.
// Pow2 levels (0,3,6,9,12,15): cell = 2^-k exactly, so x/cell == x*res exactly ->
// floorf(x*resf) is bit-identical to floorf(__fdiv_rn(x, cell)) but ~8x cheaper.
__global__ void __launch_bounds__(512, 4) hashgrid_sorted_kernel(
    const float2* __restrict__ tables,
    float2* __restrict__ out, int n_pts)
{
    __shared__ float2 out_s[32][17];     // padded to dodge bank conflicts
    __shared__ int    orig_s[32];

    const int lane  = threadIdx.x & 31;
    const int level = threadIdx.x >> 5;  // 0..15 (warp-uniform)
    const int pos   = blockIdx.x * 32 + lane;

    bool valid = (pos < n_pts);
    float2 result = make_float2(0.f, 0.f);
    int orig = -1;

    if (valid) {
        float4 v = g_sortedXyz[pos];
        float x = v.x, y = v.y, z = v.z;
        orig = __float_as_int(v.w);

        float resf = c_resf[level];
        float cell = __fdiv_rn(1.0f, resf);

        // exact match to jnp.floor(x / cell)
        float fx, fy, fz;
        if ((0x9249 >> level) & 1) {     // pow2 res: levels 0,3,6,9,12,15 (warp-uniform)
            fx = floorf(x * resf);
            fy = floorf(y * resf);
            fz = floorf(z * resf);
        } else {
            fx = floorf(__fdiv_rn(x, cell));
            fy = floorf(__fdiv_rn(y, cell));
            fz = floorf(__fdiv_rn(z, cell));
        }
        int ix = (int)fx, iy = (int)fy, iz = (int)fz;

        float minx = fx * cell, miny = fy * cell, minz = fz * cell;
        float dx = __fdividef(x - minx, (minx + cell) - minx);
        float dy = __fdividef(y - miny, (miny + cell) - miny);
        float dz = __fdividef(z - minz, (minz + cell) - minz);

        unsigned hx0 = (unsigned)ix,        hx1 = hx0 + 1u;
        unsigned hy0 = (unsigned)iy * P2,   hy1 = hy0 + P2;
        unsigned hz0 = (unsigned)iz * P3,   hz1 = hz0 + P3;

        const float2* __restrict__ table = tables + ((size_t)level << 19);

        unsigned h00 = (hx0 ^ hy0 ^ hz0) & HASH_MASK;
        unsigned h01 = (hx0 ^ hy0 ^ hz1) & HASH_MASK;
        unsigned h10 = (hx0 ^ hy1 ^ hz0) & HASH_MASK;
        unsigned h11 = (hx0 ^ hy1 ^ hz1) & HASH_MASK;

        float2 e0, e1, e2, e3, e4, e5, e6, e7;

        if (!(hx0 & 1u)) {
            // ix even: x1-corner hash = h ^ 1 -> adjacent entries, one float4 each
            const float4* __restrict__ table4 = (const float4*)table;
            float4 v00 = __ldg(table4 + (h00 >> 1));
            float4 v01 = __ldg(table4 + (h01 >> 1));
            float4 v10 = __ldg(table4 + (h10 >> 1));
            float4 v11 = __ldg(table4 + (h11 >> 1));
            if (h00 & 1u) { e4 = make_float2(v00.x, v00.y); e0 = make_float2(v00.z, v00.w); }
            else          { e0 = make_float2(v00.x, v00.y); e4 = make_float2(v00.z, v00.w); }
            if (h01 & 1u) { e5 = make_float2(v01.x, v01.y); e1 = make_float2(v01.z, v01.w); }
            else          { e1 = make_float2(v01.x, v01.y); e5 = make_float2(v01.z, v01.w); }
            if (h10 & 1u) { e6 = make_float2(v10.x, v10.y); e2 = make_float2(v10.z, v10.w); }
            else          { e2 = make_float2(v10.x, v10.y); e6 = make_float2(v10.z, v10.w); }
            if (h11 & 1u) { e7 = make_float2(v11.x, v11.y); e3 = make_float2(v11.z, v11.w); }
            else          { e3 = make_float2(v11.x, v11.y); e7 = make_float2(v11.z, v11.w); }
        } else {
            unsigned g00 = (hx1 ^ hy0 ^ hz0) & HASH_MASK;
            unsigned g01 = (hx1 ^ hy0 ^ hz1) & HASH_MASK;
            unsigned g10 = (hx1 ^ hy1 ^ hz0) & HASH_MASK;
            unsigned g11 = (hx1 ^ hy1 ^ hz1) & HASH_MASK;
            e0 = __ldg(table + h00);
            e1 = __ldg(table + h01);
            e2 = __ldg(table + h10);
            e3 = __ldg(table + h11);
            e4 = __ldg(table + g00);
            e5 = __ldg(table + g01);
            e6 = __ldg(table + g10);
            e7 = __ldg(table + g11);
        }

        float c00x = fmaf(dx, e4.x - e0.x, e0.x);
        float c00y = fmaf(dx, e4.y - e0.y, e0.y);
        float c01x = fmaf(dx, e5.x - e1.x, e1.x);
        float c01y = fmaf(dx, e5.y - e1.y, e1.y);
        float c10x = fmaf(dx, e6.x - e2.x, e2.x);
        float c10y = fmaf(dx, e6.y - e2.y, e2.y);
        float c11x = fmaf(dx, e7.x - e3.x, e3.x);
        float c11y = fmaf(dx, e7.y - e3.y, e3.y);

        float c0x = fmaf(dy, c10x - c00x, c00x);
        float c0y = fmaf(dy, c10y - c00y, c00y);
        float c1x = fmaf(dy, c11x - c01x, c01x);
        float c1y = fmaf(dy, c11y - c01y, c01y);

        result = make_float2(fmaf(dz, c1x - c0x, c0x),
                             fmaf(dz, c1y - c0y, c0y));
    }

    out_s[lane][level] = result;
    if (level == 0) orig_s[lane] = orig;
    __syncthreads();

    // cooperative scatter: one full 128B line per point, streamed past L2
    int pl = threadIdx.x >> 4;           // local point 0..31
    int c  = threadIdx.x & 15;           // level/feature pair 0..15
    int o  = orig_s[pl];
    if (o >= 0) __stwt(&out[(size_t)o * 16 + c], out_s[pl][c]);
}

extern "C" void kernel_launch(void* const* d_in, const int* in_sizes, int n_in,
                              void* d_out, int out_size)
{
    const float* xyz;
    const float2* tables;
    int n_xyz_elems;
    if (in_sizes[0] < in_sizes[1]) {
        xyz = (const float*)d_in[0];
        tables = (const float2*)d_in[1];
        n_xyz_elems = in_sizes[0];
    } else {
        xyz = (const float*)d_in[1];
        tables = (const float2*)d_in[0];
        n_xyz_elems = in_sizes[1];
    }
    int n_pts = n_xyz_elems / 3;
    int n_grp = (n_pts + 3) / 4;

    hist_kernel<<<(n_grp + 255) / 256, 256>>>((const float4*)xyz, xyz, n_pts);    // #1
    scan_blocks_kernel<<<32, 1024>>>();                                           // #2
    scatter_kernel<<<(n_grp + 255) / 256, 256>>>((const float4*)xyz, xyz, n_pts); // #3
    int n_chunks = (n_pts + 31) / 32;
    hashgrid_sorted_kernel<<<n_chunks, 512>>>(tables, (float2*)d_out, n_pts);     // #4
}